// round 4
// baseline (speedup 1.0000x reference)
#include <cuda_runtime.h>
#include <math.h>

#define N_IMG 16
#define A 360
#define R 360
#define H 256
#define W 256
#define RW 12                       // 360 bits -> 12 x 32-bit words per angle
#define PIX_PER_BLOCK 1024
#define APB 12                      // angles per block in peak kernel
#define NPB (A / APB)               // 30 peak blocks per image
#define DELTA_RHO_D (2.0 * 181.01933598375618 / 359.0)   // 2*sqrt(128^2+128^2)/359

__device__ float        g_blockmax[N_IMG * NPB];         // written every run, no init needed
__device__ unsigned int g_peak[N_IMG * A * RW];

// ---------------------------------------------------------------- peak bitmask (smem-tiled)
// grid (NPB, N_IMG), block 384 = 12 warps; warp w handles angle a0+w, all 360 r.
// Emits UNthresholded local-max bits + this tile's max value (threshold applied
// lazily in dm_mask_kernel, which is exact since candidates are re-checked there).
__global__ void __launch_bounds__(384) dm_peak_kernel(const float* __restrict__ in) {
    __shared__ float s_rows[(APB + 2) * R];      // 14 x 360 floats = 20.16 KB
    __shared__ float s_red[12];

    const int n  = blockIdx.y;
    const int a0 = blockIdx.x * APB;
    const int warp = threadIdx.x >> 5;
    const int lane = threadIdx.x & 31;
    const float* img = in + (size_t)n * (A * R);

    // load rows [a0-1 .. a0+APB] into smem; out-of-range angles -> -INF
    float m = 0.0f;                              // tile max (values are in (0,1))
    for (int idx = threadIdx.x; idx < (APB + 2) * (R / 4); idx += 384) {
        int row = idx / (R / 4);                 // 0..13
        int q   = idx % (R / 4);
        int a   = a0 - 1 + row;
        float4 v;
        if (a >= 0 && a < A) {
            v = ((const float4*)(img + a * R))[q];
            m = fmaxf(m, fmaxf(fmaxf(v.x, v.y), fmaxf(v.z, v.w)));
        } else {
            v = make_float4(-INFINITY, -INFINITY, -INFINITY, -INFINITY);
        }
        ((float4*)(s_rows + row * R))[q] = v;
    }
    // block-reduce tile max -> g_blockmax (halo rows are same-image data or -INF;
    // duplication never changes a max)
    #pragma unroll
    for (int o = 16; o; o >>= 1) m = fmaxf(m, __shfl_xor_sync(0xFFFFFFFFu, m, o));
    if (lane == 0) s_red[warp] = m;
    __syncthreads();
    if (threadIdx.x < 32) {
        m = (threadIdx.x < 12) ? s_red[threadIdx.x] : 0.0f;
        #pragma unroll
        for (int o = 8; o; o >>= 1) m = fmaxf(m, __shfl_xor_sync(0xFFFFFFFFu, m, o));
        if (threadIdx.x == 0) g_blockmax[n * NPB + blockIdx.x] = m;
    }

    const int a = a0 + warp;                     // this warp's angle
    const float* rm = s_rows + warp * R;         // a-1 row
    const float* rc = rm + R;                    // a   row
    const float* rp = rc + R;                    // a+1 row
    unsigned int* dst = &g_peak[((size_t)n * A + a) * RW];

    #pragma unroll
    for (int i = 0; i < RW; i++) {
        int r = i * 32 + lane;
        bool pk = false;
        if (r < R) {
            float v = rc[r];
            pk = true;
            // same-row neighbors
            if (r > 0     && rc[r - 1] > v) pk = false;
            if (r < R - 1 && rc[r + 1] > v) pk = false;
            // adjacent-angle rows (out-of-range rows hold -INF)
            if (rm[r] > v) pk = false;
            if (r > 0     && rm[r - 1] > v) pk = false;
            if (r < R - 1 && rm[r + 1] > v) pk = false;
            if (rp[r] > v) pk = false;
            if (r > 0     && rp[r - 1] > v) pk = false;
            if (r < R - 1 && rp[r + 1] > v) pk = false;
        }
        unsigned int word = __ballot_sync(0xFFFFFFFFu, pk);
        if (lane == 0) dst[i] = word;
    }
}

// ---------------------------------------------------------------- pixel mask
// grid (H*W / PIX_PER_BLOCK, N_IMG), block 256
__global__ void __launch_bounds__(256) dm_mask_kernel(const float* __restrict__ in,
                                                      float* __restrict__ out) {
    __shared__ unsigned int s_peak[A * RW];   // 17.28 KB
    __shared__ float s_ct[A];
    __shared__ float s_st[A];
    __shared__ float s_thr;

    const int n = blockIdx.y;
    // vectorized peak load: 4320 words = 1080 uint4
    {
        const uint4* src = (const uint4*)&g_peak[(size_t)n * A * RW];
        uint4* dst = (uint4*)s_peak;
        for (int i = threadIdx.x; i < (A * RW) / 4; i += blockDim.x) dst[i] = src[i];
    }
    for (int i = threadIdx.x; i < A; i += blockDim.x) {
        float th = (float)i * (float)(M_PI / 360.0);
        s_ct[i] = cosf(th);
        s_st[i] = sinf(th);
    }
    if (threadIdx.x < 32) {
        float bm = (threadIdx.x < NPB) ? g_blockmax[n * NPB + threadIdx.x] : 0.0f;
        #pragma unroll
        for (int o = 16; o; o >>= 1) bm = fmaxf(bm, __shfl_xor_sync(0xFFFFFFFFu, bm, o));
        if (threadIdx.x == 0) s_thr = 0.5f * bm;
    }
    __syncthreads();

    const float thr       = s_thr;
    const float delta     = (float)DELTA_RHO_D;
    const float inv_delta = 1.0f / (float)DELTA_RHO_D;
    const int   base      = blockIdx.x * PIX_PER_BLOCK;
    const float* img = in + (size_t)n * (A * R);
    float* oimg = out + (size_t)n * (H * W);

    for (int pp = threadIdx.x; pp < PIX_PER_BLOCK; pp += blockDim.x) {
        int p = base + pp;
        int h = p >> 8;          // p / W, W=256
        int w = p & 255;         // p % W
        float x = (float)w - 127.5f;   // (W-1)/2
        float y = (float)h - 127.5f;   // (H-1)/2
        float res = 0.0f;

        for (int a = 0; a < A; a++) {
            float rho = s_ct[a] * x + s_st[a] * y;
            float rc  = rho * inv_delta + 180.0f;
            int fl = (int)floorf(rc);
            int lo = fl - 3;
            int hi = fl + 3;      // conservative 7-candidate window (3/delta = 2.975)
            if (lo < 0)   lo = 0;
            if (hi > R-1) hi = R - 1;
            if (lo > hi) continue;

            const unsigned int* pw = &s_peak[a * RW];
            int w0 = lo >> 5;
            int w1 = hi >> 5;
            unsigned long long pk64 = (unsigned long long)pw[w0];
            if (w1 != w0) pk64 |= ((unsigned long long)pw[w1]) << 32;
            int s0 = lo - (w0 << 5);
            int s1 = hi - (w0 << 5);   // s1 - s0 <= 6, s1 < 38
            unsigned long long m = (((1ull << (s1 - s0 + 1)) - 1ull) << s0);
            pk64 &= m;

            while (pk64) {
                int b = __ffsll((long long)pk64) - 1;
                pk64 &= pk64 - 1ull;
                int rr = (w0 << 5) + b;
                float rv = (float)(rr - 180) * delta;     // matches reference rho_vals
                if (fabsf(rho - rv) < 3.0f) {
                    // deferred threshold: confirm this local max clears 0.5*gmax
                    if (__ldg(&img[a * R + rr]) > thr) { res = 1.0f; break; }
                }
            }
            if (res != 0.0f) break;
        }
        oimg[p] = res;
    }
}

// ---------------------------------------------------------------- launch
extern "C" void kernel_launch(void* const* d_in, const int* in_sizes, int n_in,
                              void* d_out, int out_size) {
    const float* in = (const float*)d_in[0];
    float* out = (float*)d_out;

    dm_peak_kernel<<<dim3(NPB, N_IMG), 384>>>(in);
    dm_mask_kernel<<<dim3((H * W) / PIX_PER_BLOCK, N_IMG), 256>>>(in, out);
}